// round 9
// baseline (speedup 1.0000x reference)
#include <cuda_runtime.h>
#include <cstdint>

// Sinkhorn: B=8, N=2048, eps=0.01, 50 fused (u,v) iterations.
//   u_i = eps*(log_mu - LSE_j((c_ij + v_j)/eps))   (old u cancels)
//   v_j = eps*(log_mu - LSE_i((c_ij + u_i)/eps))   (old v cancels)
// Base-2 domain: x = (c + w) * S, S = 1/(eps*ln2).
// R9: matrix loads via ld.global.L2::evict_last.v4.b64 (32B per lane-load,
//     the only vector width ptxas accepts with evict_last on sm_103) so the
//     67MB batch-pair working set stays L2-resident across alternating u/v
//     passes. Shape: 1024 CTAs/launch, warp per row, 2 chunks x 4 loads.
// All __device__ scratch referenced from device code only.
// Outputs: [pi (B*N*N), -c (B*N*N), u (B*N), v (B*N)]

#define NN 2048
#define BB 8
#define SINK_S  144.26950408889634f     // 1/(eps*ln2) = 100*log2(e)
#define SINK_C0 -0.07624618986159398f   // eps*log_mu = -0.01*ln(2048)
#define SINK_C1 0.006931471805599453f   // eps*ln2

__device__ float g_u[BB * NN];
__device__ float g_v[BB * NN];
__device__ __align__(128) float g_ct[(size_t)BB * NN * NN];  // c transposed

__device__ __forceinline__ float ex2f(float x) {
    float r; asm("ex2.approx.f32 %0, %1;" : "=f"(r) : "f"(x)); return r;
}
__device__ __forceinline__ float lg2f(float x) {
    float r; asm("lg2.approx.f32 %0, %1;" : "=f"(r) : "f"(x)); return r;
}
// 32-byte streaming load (8 floats) with L2 evict-last priority.
__device__ __forceinline__ void ldg_el8(const float* p, float* o) {
    unsigned long long r0, r1, r2, r3;
    asm volatile("ld.global.L2::evict_last.v4.b64 {%0,%1,%2,%3}, [%4];"
                 : "=l"(r0), "=l"(r1), "=l"(r2), "=l"(r3) : "l"(p));
    o[0] = __uint_as_float((unsigned)r0); o[1] = __uint_as_float((unsigned)(r0 >> 32));
    o[2] = __uint_as_float((unsigned)r1); o[3] = __uint_as_float((unsigned)(r1 >> 32));
    o[4] = __uint_as_float((unsigned)r2); o[5] = __uint_as_float((unsigned)(r2 >> 32));
    o[6] = __uint_as_float((unsigned)r3); o[7] = __uint_as_float((unsigned)(r3 >> 32));
}

__global__ void __launch_bounds__(256) init_kernel() {
    int i = blockIdx.x * 256 + threadIdx.x;
    if (i < BB * NN) g_v[i] = 0.0f;
}

// ---- transpose: g_ct[b][j][i] = c[b][i][j] ----
__global__ void __launch_bounds__(256) transpose_kernel(const float* __restrict__ c) {
    __shared__ float t[32][33];
    const int b = blockIdx.z;
    const size_t base = (size_t)b * NN * NN;
    const int x = blockIdx.x * 32 + threadIdx.x;
    const int y = blockIdx.y * 32 + threadIdx.y;
    #pragma unroll
    for (int j = 0; j < 32; j += 8)
        t[threadIdx.y + j][threadIdx.x] = c[base + (size_t)(y + j) * NN + x];
    __syncthreads();
    const int x2 = blockIdx.y * 32 + threadIdx.x;
    const int y2 = blockIdx.x * 32 + threadIdx.y;
    #pragma unroll
    for (int j = 0; j < 32; j += 8)
        g_ct[base + (size_t)(y2 + j) * NN + x2] = t[threadIdx.x][threadIdx.y + j];
}

// ---- LSE pass. UPASS=true:  mat=c,    vec=g_v, out=g_u.
//                UPASS=false: mat=g_ct, vec=g_u, out=g_v (clamped).
// 2 batches per launch, 512 CTAs per batch, 4 rows per CTA (warp per row),
// each warp covers its row in 2 chunks of 4 x 32B loads (8 floats each).
template <bool UPASS>
__global__ void __launch_bounds__(128, 9) pass_kernel(const float* __restrict__ cmat,
                                                      int b0) {
    const int b  = b0 + (blockIdx.x >> 9);       // 512 CTAs per batch
    const int r0 = (blockIdx.x & 511) * 4;

    const float* vec = UPASS ? g_v : g_u;        // device-side symbol refs only
    const float* mat = UPASS ? cmat : g_ct;
    float*       out = UPASS ? g_u : g_v;

    const int warp = threadIdx.x >> 5, lane = threadIdx.x & 31;
    const int row = r0 + warp;
    const float* __restrict__ crow = mat + ((size_t)b * NN + row) * NN;
    const float* __restrict__ vvec = vec + b * NN;

    float m = -1e30f, s = 0.0f;
    #pragma unroll
    for (int h = 0; h < 2; h++) {
        // Phase 0: front-batched matrix loads for this chunk (4 x 32B, MLP=4x8B-lanes)
        float xv[32];
        #pragma unroll
        for (int k = 0; k < 4; k++)
            ldg_el8(crow + (h * 4 + k) * 256 + lane * 8, xv + k * 8);

        // Phase 1: x = (c + w) * S, chunk max tree (w loads hit L1)
        float m0 = -1e30f, m1 = -1e30f, m2 = -1e30f, m3 = -1e30f;
        #pragma unroll
        for (int k = 0; k < 4; k++) {
            const float4* wp = reinterpret_cast<const float4*>(
                vvec + (h * 4 + k) * 256 + lane * 8);
            float4 wa = wp[0], wb = wp[1];
            float* x = xv + k * 8;
            x[0] = (x[0] + wa.x) * SINK_S;
            x[1] = (x[1] + wa.y) * SINK_S;
            x[2] = (x[2] + wa.z) * SINK_S;
            x[3] = (x[3] + wa.w) * SINK_S;
            x[4] = (x[4] + wb.x) * SINK_S;
            x[5] = (x[5] + wb.y) * SINK_S;
            x[6] = (x[6] + wb.z) * SINK_S;
            x[7] = (x[7] + wb.w) * SINK_S;
            m0 = fmaxf(m0, fmaxf(x[0], x[4]));
            m1 = fmaxf(m1, fmaxf(x[1], x[5]));
            m2 = fmaxf(m2, fmaxf(x[2], x[6]));
            m3 = fmaxf(m3, fmaxf(x[3], x[7]));
        }
        float cm = fmaxf(fmaxf(m0, m1), fmaxf(m2, m3));

        // Phase 2: chunk exp2 sum, 4 independent accumulators
        float s0 = 0.f, s1 = 0.f, s2 = 0.f, s3 = 0.f;
        #pragma unroll
        for (int k = 0; k < 4; k++) {
            const float* x = xv + k * 8;
            s0 += ex2f(x[0] - cm) + ex2f(x[4] - cm);
            s1 += ex2f(x[1] - cm) + ex2f(x[5] - cm);
            s2 += ex2f(x[2] - cm) + ex2f(x[6] - cm);
            s3 += ex2f(x[3] - cm) + ex2f(x[7] - cm);
        }
        float cs = (s0 + s1) + (s2 + s3);

        // combine chunk into running (m, s)
        float mm = fmaxf(m, cm);
        s = fmaf(s, ex2f(m - mm), cs * ex2f(cm - mm));
        m = mm;
    }

    // warp butterfly combine of (m, s)
    #pragma unroll
    for (int off = 16; off; off >>= 1) {
        float m2 = __shfl_xor_sync(0xffffffffu, m, off);
        float s2 = __shfl_xor_sync(0xffffffffu, s, off);
        float mm = fmaxf(m, m2);
        s = fmaf(s, ex2f(m - mm), s2 * ex2f(m2 - mm));
        m = mm;
    }

    if (lane == 0) {
        float r = fmaf(-SINK_C1, m + lg2f(s), SINK_C0);
        if (!UPASS && r > 9e8f) r = 0.0f;   // reference clamp on v
        out[b * NN + row] = r;
    }
}

// ---- epilogue: pi = exp2((c+u+v)*S), -c, u, v ----
__global__ void __launch_bounds__(128) final_kernel(const float* __restrict__ c,
                                                    float* __restrict__ out) {
    const size_t BNN = (size_t)BB * NN * NN;
    const int rowid = blockIdx.x;
    const int b = rowid >> 11;
    const float u = g_u[rowid];
    const float4* __restrict__ crow =
        reinterpret_cast<const float4*>(c + (size_t)rowid * NN);
    const float4* __restrict__ vrow =
        reinterpret_cast<const float4*>(g_v + (size_t)b * NN);
    float4* pio = reinterpret_cast<float4*>(out + (size_t)rowid * NN);
    float4* nco = reinterpret_cast<float4*>(out + BNN + (size_t)rowid * NN);

    #pragma unroll 2
    for (int t = threadIdx.x; t < NN / 4; t += 128) {
        float4 cc = crow[t];
        float4 vv = vrow[t];
        float4 pi, nc;
        pi.x = ex2f(((cc.x + u) + vv.x) * SINK_S);
        pi.y = ex2f(((cc.y + u) + vv.y) * SINK_S);
        pi.z = ex2f(((cc.z + u) + vv.z) * SINK_S);
        pi.w = ex2f(((cc.w + u) + vv.w) * SINK_S);
        nc.x = -cc.x; nc.y = -cc.y; nc.z = -cc.z; nc.w = -cc.w;
        pio[t] = pi;
        nco[t] = nc;
    }
    int gid = blockIdx.x * 128 + threadIdx.x;
    if (gid < BB * NN) {
        out[2 * BNN + gid] = g_u[gid];
        out[2 * BNN + (size_t)BB * NN + gid] = g_v[gid];
    }
}

extern "C" void kernel_launch(void* const* d_in, const int* in_sizes, int n_in,
                              void* d_out, int out_size) {
    const float* c = (const float*)d_in[0];

    init_kernel<<<(BB * NN + 255) / 256, 256>>>();
    transpose_kernel<<<dim3(NN / 32, NN / 32, BB), dim3(32, 8)>>>(c);

    // 4 serialized batch-pairs: per-pass working set ~67MB, pinned in L2
    // via evict_last matrix loads.
    for (int pr = 0; pr < 4; ++pr) {
        const int b0 = pr * 2;
        for (int it = 0; it < 50; ++it) {
            pass_kernel<true ><<<2 * 512, 128>>>(c, b0);   // u-pass
            pass_kernel<false><<<2 * 512, 128>>>(c, b0);   // v-pass
        }
    }
    final_kernel<<<BB * NN, 128>>>(c, (float*)d_out);
}